// round 5
// baseline (speedup 1.0000x reference)
#include <cuda_runtime.h>

#define BB 32
#define SS 2048
#define DD 1024
#define KATT 10
#define CHUNKS 32
#define ROWS_PER_CHUNK (SS / CHUNKS)   // 64
#define D4 (DD / 4)                    // 256 float4 per row

// Scratch (no allocation allowed)
__device__ float g_partial[BB * CHUNKS * DD];  // 4 MB
__device__ float g_vraw[BB * DD];
__device__ float g_vn[BB * DD];
__device__ float g_corr[BB * DD];

// ---------------------------------------------------------------------------
// k1: partial sums over sequence chunks.
// grid = BB*CHUNKS blocks, 256 threads. Block (b,c) sums 64 rows of [b].
// ---------------------------------------------------------------------------
__global__ void __launch_bounds__(256) k1_partial(const float* __restrict__ h) {
    const float4* h4 = (const float4*)h;
    int b = blockIdx.x >> 5;
    int c = blockIdx.x & 31;
    const float4* p = h4 + ((size_t)b << 19) + (size_t)c * ROWS_PER_CHUNK * D4 + threadIdx.x;
    float4 acc = make_float4(0.f, 0.f, 0.f, 0.f);
#pragma unroll 8
    for (int s = 0; s < ROWS_PER_CHUNK; ++s) {
        float4 v = __ldcs(&p[(size_t)s * D4]);
        acc.x += v.x; acc.y += v.y; acc.z += v.z; acc.w += v.w;
    }
    ((float4*)g_partial)[(b * CHUNKS + c) * D4 + threadIdx.x] = acc;
}

// ---------------------------------------------------------------------------
// k1b: reduce the 32 chunk-partials -> v_raw (mean over S).
// grid = BB blocks, 256 threads.
// ---------------------------------------------------------------------------
__global__ void __launch_bounds__(256) k1b_reduce() {
    int b = blockIdx.x;
    int t = threadIdx.x;
    const float4* p4 = (const float4*)g_partial;
    float4 acc = make_float4(0.f, 0.f, 0.f, 0.f);
#pragma unroll
    for (int c = 0; c < CHUNKS; ++c) {
        float4 v = p4[(b * CHUNKS + c) * D4 + t];
        acc.x += v.x; acc.y += v.y; acc.z += v.z; acc.w += v.w;
    }
    const float inv = 1.0f / (float)SS;
    acc.x *= inv; acc.y *= inv; acc.z *= inv; acc.w *= inv;
    ((float4*)g_vraw)[b * D4 + t] = acc;
}

// ---------------------------------------------------------------------------
// k2: all the small math. One block, 1024 threads (32 warps).
//   phase 0: attractor norm scales (warps 0..9)
//   phase A: whitening over batch — 256 threads x float4 (vectorized)
//   phase B: cosine + argmax (warp w handles batch row w)
//   phase C: correction = v_snapped - v_raw — 256 threads x float4
// ---------------------------------------------------------------------------
__global__ void __launch_bounds__(1024, 1) k2_small(const float* __restrict__ att) {
    __shared__ float s_s1[KATT];    // 1/max(|a|,1e-8)
    __shared__ float s_cs[KATT];    // combined cosine scale: s1 / max(|a|*s1, 1e-12)
    __shared__ float s_alpha[BB];
    __shared__ int   s_best[BB];

    int tid = threadIdx.x;
    int lane = tid & 31;
    int wid = tid >> 5;

    // --- phase 0: attractor scales ---
    if (wid < KATT) {
        float s = 0.f;
        for (int j = lane; j < DD; j += 32) {
            float a = att[wid * DD + j];
            s += a * a;
        }
#pragma unroll
        for (int o = 16; o; o >>= 1) s += __shfl_xor_sync(0xffffffff, s, o);
        if (lane == 0) {
            float n1 = sqrtf(s);
            float s1 = 1.0f / fmaxf(n1, 1e-8f);
            float n2 = n1 * s1;                 // |att| after first normalize
            s_s1[wid] = s1;
            s_cs[wid] = s1 / fmaxf(n2, 1e-12f);
        }
    }

    // --- phase A: whitening (two-pass mean/var, float4: thread t of first 256
    //              handles dims [4t, 4t+4) across all 32 batch rows) ---
    if (tid < 256) {
        const float4* vr4 = (const float4*)g_vraw;
        float4* vn4 = (float4*)g_vn;
        float4 sum = make_float4(0.f, 0.f, 0.f, 0.f);
#pragma unroll
        for (int b = 0; b < BB; ++b) {
            float4 v = vr4[b * D4 + tid];
            sum.x += v.x; sum.y += v.y; sum.z += v.z; sum.w += v.w;
        }
        const float invB = 1.0f / (float)BB;
        float4 mean = make_float4(sum.x * invB, sum.y * invB, sum.z * invB, sum.w * invB);
        float4 s2 = make_float4(0.f, 0.f, 0.f, 0.f);
#pragma unroll
        for (int b = 0; b < BB; ++b) {
            float4 v = vr4[b * D4 + tid];
            float tx = v.x - mean.x, ty = v.y - mean.y, tz = v.z - mean.z, tw = v.w - mean.w;
            s2.x += tx * tx; s2.y += ty * ty; s2.z += tz * tz; s2.w += tw * tw;
        }
        float4 inv;
        inv.x = 1.0f / sqrtf(s2.x * invB + 1e-8f);
        inv.y = 1.0f / sqrtf(s2.y * invB + 1e-8f);
        inv.z = 1.0f / sqrtf(s2.z * invB + 1e-8f);
        inv.w = 1.0f / sqrtf(s2.w * invB + 1e-8f);
#pragma unroll
        for (int b = 0; b < BB; ++b) {
            float4 v = vr4[b * D4 + tid];
            float4 o;
            o.x = (v.x - mean.x) * inv.x;
            o.y = (v.y - mean.y) * inv.y;
            o.z = (v.z - mean.z) * inv.z;
            o.w = (v.w - mean.w) * inv.w;
            vn4[b * D4 + tid] = o;
        }
    }
    __syncthreads();

    // --- phase B: cosine similarity + argmax (warp w -> batch row w) ---
    {
        int b = wid;
        float vnr[32];
#pragma unroll
        for (int j = 0; j < 32; ++j) vnr[j] = g_vn[b * DD + lane + 32 * j];
        float best = -1e30f;
        int bi = 0;
        for (int k = 0; k < KATT; ++k) {
            float p = 0.f;
#pragma unroll
            for (int j = 0; j < 32; ++j) p += vnr[j] * att[k * DD + lane + 32 * j];
#pragma unroll
            for (int o = 16; o; o >>= 1) p += __shfl_xor_sync(0xffffffff, p, o);
            float cosv = p * s_cs[k];
            if (cosv > best) { best = cosv; bi = k; }   // first max (strict >) == jnp.argmax
        }
        if (lane == 0) {
            s_alpha[b] = 0.3f * (1.0f - best);
            s_best[b] = bi;
        }
    }
    __syncthreads();

    // --- phase C: correction = v_norm + alpha*clip(closest - v_norm) - v_raw ---
    if (tid < 256) {
        const float4* vr4 = (const float4*)g_vraw;
        const float4* vn4 = (const float4*)g_vn;
        const float4* at4 = (const float4*)att;
        float4* co4 = (float4*)g_corr;
#pragma unroll
        for (int b = 0; b < BB; ++b) {
            float4 vn = vn4[b * D4 + tid];
            float4 vr = vr4[b * D4 + tid];
            int k = s_best[b];
            float s1 = s_s1[k];
            float al = s_alpha[b];
            float4 a = at4[k * D4 + tid];
            float4 o;
            float dx = fminf(fmaxf(a.x * s1 - vn.x, -0.5f), 0.5f);
            float dy = fminf(fmaxf(a.y * s1 - vn.y, -0.5f), 0.5f);
            float dz = fminf(fmaxf(a.z * s1 - vn.z, -0.5f), 0.5f);
            float dw = fminf(fmaxf(a.w * s1 - vn.w, -0.5f), 0.5f);
            o.x = vn.x + al * dx - vr.x;
            o.y = vn.y + al * dy - vr.y;
            o.z = vn.z + al * dz - vr.z;
            o.w = vn.w + al * dw - vr.w;
            co4[b * D4 + tid] = o;
        }
    }
}

// ---------------------------------------------------------------------------
// k3: out[b][s][d] = h[b][s][d] + corr[b][d], 4 float4 per thread.
// Each block covers 1024 CONTIGUOUS float4 (16 KB): thread t handles
// base+{0,256,512,768}. Since 1024 divides 2^19 (float4 per batch), b is
// uniform per block; and all four offsets are == tid (mod 256), so ONE corr
// load per thread feeds all 4 stores.
// grid = 16384 blocks x 256 threads; coverage = 16384*1024 = 2^24 float4.
// ---------------------------------------------------------------------------
__global__ void __launch_bounds__(256) k3_apply(const float* __restrict__ h,
                                                float* __restrict__ out) {
    const float4* h4 = (const float4*)h;
    float4* o4 = (float4*)out;
    unsigned base = blockIdx.x * 1024u + threadIdx.x;     // float4 index
    // front-batched loads (MLP_p1 = 4)
    float4 v0 = __ldcs(&h4[base]);
    float4 v1 = __ldcs(&h4[base + 256]);
    float4 v2 = __ldcs(&h4[base + 512]);
    float4 v3 = __ldcs(&h4[base + 768]);
    unsigned b = base >> 19;                 // uniform per block
    float4 c = ((const float4*)g_corr)[(b << 8) + threadIdx.x];  // d4 == tid for all 4
    v0.x += c.x; v0.y += c.y; v0.z += c.z; v0.w += c.w;
    v1.x += c.x; v1.y += c.y; v1.z += c.z; v1.w += c.w;
    v2.x += c.x; v2.y += c.y; v2.z += c.z; v2.w += c.w;
    v3.x += c.x; v3.y += c.y; v3.z += c.z; v3.w += c.w;
    __stcs(&o4[base], v0);
    __stcs(&o4[base + 256], v1);
    __stcs(&o4[base + 512], v2);
    __stcs(&o4[base + 768], v3);
}

// ---------------------------------------------------------------------------
extern "C" void kernel_launch(void* const* d_in, const int* in_sizes, int n_in,
                              void* d_out, int out_size) {
    const float* hidden = (const float*)d_in[0];   // [32, 2048, 1024] f32
    const float* att    = (const float*)d_in[1];   // [10, 1024] f32
    float* out = (float*)d_out;

    k1_partial<<<BB * CHUNKS, 256>>>(hidden);
    k1b_reduce<<<BB, 256>>>();
    k2_small<<<1, 1024>>>(att);
    const unsigned total4 = (unsigned)BB * SS * D4;       // 16,777,216 float4
    k3_apply<<<total4 / 1024, 256>>>(hidden, out);        // 16384 blocks
}